// round 15
// baseline (speedup 1.0000x reference)
#include <cuda_runtime.h>
#include <cuda_fp16.h>
#include <cstdint>

#define KDIM 4096
#define CDIM 4096
#define BROWS 8192
#define EPSV 1e-5f

#define BMt 128
#define BNt 128
#define TPB 256
#define NSTG 4
#define STG_B 24576         // Ah(8K) Al(8K) Bh(8K)
#define NKT (KDIM / 32)     // 128

// fp16 limb scratch (device globals: sanctioned no-alloc workaround)
__device__ __half g_xh[(size_t)BROWS * KDIM];
__device__ __half g_xl[(size_t)BROWS * KDIM];
__device__ __half g_wh[(size_t)CDIM * KDIM];

// ---------------- helpers ----------------
__device__ __forceinline__ uint32_t s2u(const void* p) {
    uint32_t a;
    asm("{ .reg .u64 t; cvta.to.shared.u64 t, %1; cvt.u32.u64 %0, t; }"
        : "=r"(a) : "l"(p));
    return a;
}
__device__ __forceinline__ void cp16(uint32_t d, const void* s) {
    asm volatile("cp.async.cg.shared.global [%0], [%1], 16;" :: "r"(d), "l"(s));
}
__device__ __forceinline__ void cp_commit() {
    asm volatile("cp.async.commit_group;" ::: "memory");
}
template <int N> __device__ __forceinline__ void cp_wait() {
    asm volatile("cp.async.wait_group %0;" :: "n"(N) : "memory");
}
__device__ __forceinline__ void ldsm4(uint32_t* r, uint32_t a) {
    asm volatile("ldmatrix.sync.aligned.m8n8.x4.shared.b16 {%0,%1,%2,%3}, [%4];"
        : "=r"(r[0]), "=r"(r[1]), "=r"(r[2]), "=r"(r[3]) : "r"(a));
}
__device__ __forceinline__ void mma16816(float* d, const uint32_t* a,
                                         uint32_t b0, uint32_t b1) {
    asm volatile("mma.sync.aligned.m16n8k16.row.col.f32.f16.f16.f32 "
        "{%0,%1,%2,%3}, {%4,%5,%6,%7}, {%8,%9}, {%0,%1,%2,%3};"
        : "+f"(d[0]), "+f"(d[1]), "+f"(d[2]), "+f"(d[3])
        : "r"(a[0]), "r"(a[1]), "r"(a[2]), "r"(a[3]), "r"(b0), "r"(b1));
}

// ---------------- convert kernel (single launch for x and w) ----------------
__global__ void __launch_bounds__(256)
k_convert(const float* __restrict__ x, const float* __restrict__ w,
          __half2* __restrict__ xh, __half2* __restrict__ xl,
          __half2* __restrict__ wh, size_t n4x, size_t n4tot) {
    size_t i = (size_t)blockIdx.x * blockDim.x + threadIdx.x;
    size_t stride = (size_t)gridDim.x * blockDim.x;
    for (; i < n4tot; i += stride) {
        if (i < n4x) {
            float4 v = ((const float4*)x)[i];
            __half h0 = __float2half_rn(v.x), h1 = __float2half_rn(v.y);
            __half h2 = __float2half_rn(v.z), h3 = __float2half_rn(v.w);
            __half l0 = __float2half_rn(v.x - __half2float(h0));
            __half l1 = __float2half_rn(v.y - __half2float(h1));
            __half l2 = __float2half_rn(v.z - __half2float(h2));
            __half l3 = __float2half_rn(v.w - __half2float(h3));
            xh[i * 2 + 0] = __halves2half2(h0, h1);
            xh[i * 2 + 1] = __halves2half2(h2, h3);
            xl[i * 2 + 0] = __halves2half2(l0, l1);
            xl[i * 2 + 1] = __halves2half2(l2, l3);
        } else {
            size_t idx = i - n4x;
            float4 v = ((const float4*)w)[idx];
            wh[idx * 2 + 0] = __halves2half2(__float2half_rn(v.x),
                                             __float2half_rn(v.y));
            wh[idx * 2 + 1] = __halves2half2(__float2half_rn(v.z),
                                             __float2half_rn(v.w));
        }
    }
}

// ---------------- fused GEMM (HMMA fp16 2-product, eighth-burst prefetch) ----------------
__global__ void __launch_bounds__(TPB, 2)
gemm_hmma(const float* __restrict__ bias, const float* __restrict__ gnw,
          const float* __restrict__ gnb, const float* __restrict__ mw,
          float* __restrict__ out) {
    extern __shared__ char smraw[];
    const uint32_t smb = s2u(smraw);

    const int tid = threadIdx.x;
    const int lane = tid & 31;
    const int wid = tid >> 5;
    const int warpM = wid >> 1;     // 0..3  (32 rows each)
    const int warpN = wid & 1;      // 0..1  (64 cols each)
    const int rowBase = blockIdx.y * BMt;
    const int colBase = blockIdx.x * BNt;

    // ---- loader mapping (proven R9) ----
    const bool isA = tid < 128;
    const int t6 = tid & 63;
    const int arowL = t6 >> 2;          // 0..15
    const int achunk = t6 & 3;
    const int wrowL = tid & 127;

    const char* gsrcA = (const char*)((tid < 64) ? g_xh : g_xl)
                      + (size_t)(rowBase + arowL) * (KDIM * 2) + achunk * 16;
    const uint32_t ldstA = smb + ((tid < 64) ? 0 : 8192) + arowL * 64
                         + (uint32_t)((achunk ^ ((arowL >> 1) & 3)) << 4);

    const char* gsrcW = (const char*)g_wh
                      + (size_t)(colBase + wrowL) * (KDIM * 2);
    const uint32_t wkey = (uint32_t)((wrowL >> 1) & 3);
    const uint32_t ldstW = smb + 16384 + wrowL * 64;

    // full chunk load (prologue only); NO commit
#define LOAD_ONE(kt_, s_) do {                                              \
        if (isA) {                                                          \
            const char* p_ = gsrcA + (size_t)(kt_) * 64;                    \
            uint32_t d_ = ldstA + (uint32_t)(s_) * STG_B;                   \
            _Pragma("unroll")                                               \
            for (int j_ = 0; j_ < 8; j_++)                                  \
                cp16(d_ + j_ * 1024, p_ + (size_t)j_ * 16 * (KDIM * 2));    \
        } else {                                                            \
            const char* p_ = gsrcW + (size_t)(kt_) * 64;                    \
            uint32_t d_ = ldstW + (uint32_t)(s_) * STG_B;                   \
            _Pragma("unroll")                                               \
            for (int j_ = 0; j_ < 4; j_++)                                  \
                cp16(d_ + ((((uint32_t)j_) ^ wkey) << 4), p_ + j_ * 16);    \
        }                                                                   \
    } while (0)

    // eighth-step load of the pair at (pfA/pfW, dfA/dfW); st_ in 0..7
    // A threads: 2 cp16 per step; W threads: 1 cp16 per step
    // (chunk pair occupies slots base, base+1: (kt0+2)&3 is even)
    // NOTE: st_ is a fully-unrolled loop index — constant-folded by ptxas,
    // but NOT a C++ constant expression, so plain int (not constexpr).
#define LOAD_STEP8(st_) do {                                                \
        if (isA) {                                                          \
            _Pragma("unroll")                                               \
            for (int u_ = 0; u_ < 2; u_++) {                                \
                int idx_ = (st_) * 2 + u_;                                  \
                int c_ = idx_ >> 3, j_ = idx_ & 7;                          \
                cp16(dfA + c_ * STG_B + j_ * 1024,                          \
                     pfA + c_ * 64 + (size_t)j_ * 16 * (KDIM * 2));         \
            }                                                               \
        } else {                                                            \
            int c_ = (st_) >> 2, j_ = (st_) & 3;                            \
            cp16(dfW + c_ * STG_B + ((((uint32_t)j_) ^ wkey) << 4),         \
                 pfW + c_ * 64 + j_ * 16);                                  \
        }                                                                   \
    } while (0)

    // ---- ldsm lane address precompute ----
    uint32_t arow[2], akey[2];
#pragma unroll
    for (int mt = 0; mt < 2; mt++) {
        int r = warpM * 32 + mt * 16 + (lane & 7) + ((lane >> 3) & 1) * 8;
        arow[mt] = (uint32_t)(r * 64);
        akey[mt] = (uint32_t)((r >> 1) & 3);
    }
    const uint32_t asel = (uint32_t)((lane >> 4) & 1);
    uint32_t brow[4], bkey[4];
#pragma unroll
    for (int p = 0; p < 4; p++) {
        int r = warpN * 64 + p * 16 + (lane & 7) + ((lane >> 4) & 1) * 8;
        brow[p] = (uint32_t)(r * 64);
        bkey[p] = (uint32_t)((r >> 1) & 3);
    }
    const uint32_t bsel = (uint32_t)((lane >> 3) & 1);

    float acc[16][4];
#pragma unroll
    for (int i = 0; i < 16; i++)
#pragma unroll
        for (int j = 0; j < 4; j++) acc[i][j] = 0.f;

    LOAD_ONE(0, 0);
    LOAD_ONE(1, 1);
    cp_commit();                // kt 0,1 -> slots 0,1 (one group)

    for (int it = 0; it < NKT / 2; it++) {
        const int kt0 = 2 * it;
        cp_wait<0>();           // group for kt0,kt0+1 resident (committed mid-prev it)
        __syncthreads();        // reads of the other group finished

        // hoisted prefetch addressing for the (kt0+2, kt0+3) pair
        const bool pf = (kt0 + 2 < NKT);
        const char* pfA = gsrcA + (size_t)(kt0 + 2) * 64;
        const char* pfW = gsrcW + (size_t)(kt0 + 2) * 64;
        const uint32_t dfA = ldstA + (uint32_t)((kt0 + 2) & 3) * STG_B;
        const uint32_t dfW = ldstW + (uint32_t)((kt0 + 2) & 3) * STG_B;

#pragma unroll
        for (int q = 0; q < 2; q++) {
            const uint32_t Ab = smb + (uint32_t)((kt0 + q) & 3) * STG_B;
            const uint32_t Bb = Ab + 16384;
#pragma unroll
            for (int s = 0; s < 2; s++) {
                uint32_t ah[2][4], al[2][4], bh[8][2];
                // ALL fragment loads upfront: al latency hidden by ah-mma block
#pragma unroll
                for (int mt = 0; mt < 2; mt++) {
                    uint32_t ad = Ab + arow[mt]
                                + ((((uint32_t)s * 2 + asel) ^ akey[mt]) << 4);
                    ldsm4(ah[mt], ad);
                    ldsm4(al[mt], ad + 8192);
                }
#pragma unroll
                for (int p = 0; p < 4; p++) {
                    uint32_t bd = Bb + brow[p]
                                + ((((uint32_t)s * 2 + bsel) ^ bkey[p]) << 4);
                    uint32_t r1[4];
                    ldsm4(r1, bd);
                    bh[2 * p][0] = r1[0]; bh[2 * p][1] = r1[1];
                    bh[2 * p + 1][0] = r1[2]; bh[2 * p + 1][1] = r1[3];
                }

                // ah-mma, half 1 (mt=0)
#pragma unroll
                for (int nt = 0; nt < 8; nt++)
                    mma16816(acc[nt], ah[0], bh[nt][0], bh[nt][1]);
                if (q == 0 && pf) LOAD_STEP8(s * 4 + 0);
                // ah-mma, half 2 (mt=1)
#pragma unroll
                for (int nt = 0; nt < 8; nt++)
                    mma16816(acc[8 + nt], ah[1], bh[nt][0], bh[nt][1]);
                if (q == 0 && pf) LOAD_STEP8(s * 4 + 1);
                // al-mma, half 1 (mt=0)
#pragma unroll
                for (int nt = 0; nt < 8; nt++)
                    mma16816(acc[nt], al[0], bh[nt][0], bh[nt][1]);
                if (q == 0 && pf) LOAD_STEP8(s * 4 + 2);
                // al-mma, half 2 (mt=1)
#pragma unroll
                for (int nt = 0; nt < 8; nt++)
                    mma16816(acc[8 + nt], al[1], bh[nt][0], bh[nt][1]);
                if (q == 0 && pf) {
                    LOAD_STEP8(s * 4 + 3);
                    if (s == 1) cp_commit();   // full q1 of slack before the wait
                }
            }
        }
    }

    // ---------------- fused epilogue ----------------
    float biasv[16];
#pragma unroll
    for (int nt = 0; nt < 8; nt++) {
        int c0 = colBase + warpN * 64 + nt * 8 + 2 * (lane & 3);
        biasv[nt * 2]     = __ldg(bias + c0);
        biasv[nt * 2 + 1] = __ldg(bias + c0 + 1);
    }
#pragma unroll
    for (int mt = 0; mt < 2; mt++)
#pragma unroll
        for (int nt = 0; nt < 8; nt++) {
            acc[mt * 8 + nt][0] += biasv[nt * 2];
            acc[mt * 8 + nt][1] += biasv[nt * 2 + 1];
            acc[mt * 8 + nt][2] += biasv[nt * 2];
            acc[mt * 8 + nt][3] += biasv[nt * 2 + 1];
        }

    // per-thread partial row sums over this warp's 64 columns
    float rs[4], rq[4];
#pragma unroll
    for (int mt = 0; mt < 2; mt++) {
        float s0 = 0.f, q0 = 0.f, s1 = 0.f, q1 = 0.f;
#pragma unroll
        for (int nt = 0; nt < 8; nt++) {
            float v;
            v = acc[mt * 8 + nt][0]; s0 += v; q0 += v * v;
            v = acc[mt * 8 + nt][1]; s0 += v; q0 += v * v;
            v = acc[mt * 8 + nt][2]; s1 += v; q1 += v * v;
            v = acc[mt * 8 + nt][3]; s1 += v; q1 += v * v;
        }
        rs[mt * 2] = s0; rq[mt * 2] = q0;
        rs[mt * 2 + 1] = s1; rq[mt * 2 + 1] = q1;
    }
#pragma unroll
    for (int off = 1; off <= 2; off <<= 1)
#pragma unroll
        for (int i = 0; i < 4; i++) {
            rs[i] += __shfl_xor_sync(0xffffffffu, rs[i], off);
            rq[i] += __shfl_xor_sync(0xffffffffu, rq[i], off);
        }

    float2* red = (float2*)smraw;        // [128][2]
    __syncthreads();
    if ((lane & 3) == 0) {
#pragma unroll
        for (int mt = 0; mt < 2; mt++)
#pragma unroll
            for (int h = 0; h < 2; h++) {
                int rowL = warpM * 32 + mt * 16 + (lane >> 2) + h * 8;
                red[rowL * 2 + warpN] = make_float2(rs[mt * 2 + h], rq[mt * 2 + h]);
            }
    }
    __syncthreads();

    float meanv[4], rstdv[4];
#pragma unroll
    for (int mt = 0; mt < 2; mt++)
#pragma unroll
        for (int h = 0; h < 2; h++) {
            int rowL = warpM * 32 + mt * 16 + (lane >> 2) + h * 8;
            float2 t0 = red[rowL * 2 + 0];
            float2 t1 = red[rowL * 2 + 1];
            float s = t0.x + t1.x, q = t0.y + t1.y;
            float m = s * (1.0f / 128.0f);
            float var = q * (1.0f / 128.0f) - m * m;
            meanv[mt * 2 + h] = m;
            rstdv[mt * 2 + h] = rsqrtf(var + EPSV);
        }

    float gwv[16], gbv[16], mwv[16];
#pragma unroll
    for (int nt = 0; nt < 8; nt++) {
        int c0 = colBase + warpN * 64 + nt * 8 + 2 * (lane & 3);
        gwv[nt * 2] = __ldg(gnw + c0);   gwv[nt * 2 + 1] = __ldg(gnw + c0 + 1);
        gbv[nt * 2] = __ldg(gnb + c0);   gbv[nt * 2 + 1] = __ldg(gnb + c0 + 1);
        mwv[nt * 2] = __ldg(mw + c0);    mwv[nt * 2 + 1] = __ldg(mw + c0 + 1);
    }

#pragma unroll
    for (int mt = 0; mt < 2; mt++)
#pragma unroll
        for (int h = 0; h < 2; h++) {
            const int r = rowBase + warpM * 32 + mt * 16 + (lane >> 2) + h * 8;
            const float m = meanv[mt * 2 + h];
            const float rstd = rstdv[mt * 2 + h];
#pragma unroll
            for (int nt = 0; nt < 8; nt++) {
                const int c0 = colBase + warpN * 64 + nt * 8 + 2 * (lane & 3);
                float o2[2];
#pragma unroll
                for (int j = 0; j < 2; j++) {
                    float v = acc[mt * 8 + nt][h * 2 + j];
                    float hn = (v - m) * rstd;
                    hn = fmaf(hn, gwv[nt * 2 + j], gbv[nt * 2 + j]);
                    float x1 = __fdividef(hn, 1.0f + __expf(-hn));
                    float x2 = x1 * mwv[nt * 2 + j];
                    o2[j] = __fdividef(x2, 1.0f + __expf(-x2));
                }
                *(float2*)(out + (size_t)r * CDIM + c0) = make_float2(o2[0], o2[1]);
            }
        }
}

extern "C" void kernel_launch(void* const* d_in, const int* in_sizes, int n_in,
                              void* d_out, int out_size) {
    const float* x    = (const float*)d_in[0];
    const float* w    = (const float*)d_in[1];
    const float* bias = (const float*)d_in[2];
    const float* gnw  = (const float*)d_in[3];
    const float* gnb  = (const float*)d_in[4];
    const float* mw   = (const float*)d_in[5];
    float* out = (float*)d_out;

    const int rows = in_sizes[0] / KDIM;   // 8192

    __half *xh, *xl, *wh;
    cudaGetSymbolAddress((void**)&xh, g_xh);
    cudaGetSymbolAddress((void**)&xl, g_xl);
    cudaGetSymbolAddress((void**)&wh, g_wh);

    const size_t n4x = (size_t)rows * KDIM / 4;
    const size_t n4w = (size_t)CDIM * KDIM / 4;
    k_convert<<<4096, 256>>>(x, w, (__half2*)xh, (__half2*)xl,
                             (__half2*)wh, n4x, n4x + n4w);

    const int smem = NSTG * STG_B;     // 98304
    cudaFuncSetAttribute(gemm_hmma,
                         cudaFuncAttributeMaxDynamicSharedMemorySize, smem);

    dim3 grid(CDIM / BNt, rows / BMt);  // 32 x 64
    gemm_hmma<<<grid, TPB, smem>>>(bias, gnw, gnb, mw, out);
}

// round 16
// speedup vs baseline: 1.0246x; 1.0246x over previous
#include <cuda_runtime.h>
#include <cuda_fp16.h>
#include <cstdint>

#define KDIM 4096
#define CDIM 4096
#define BROWS 8192
#define EPSV 1e-5f

#define BMt 128
#define BNt 128
#define TPB 256
#define NSTG 4
#define STG_B 24576         // Ah(8K) Al(8K) Bh(8K)
#define NKT (KDIM / 32)     // 128

// fp16 limb scratch (device globals: sanctioned no-alloc workaround)
__device__ __half g_xh[(size_t)BROWS * KDIM];
__device__ __half g_xl[(size_t)BROWS * KDIM];
__device__ __half g_wh[(size_t)CDIM * KDIM];

// ---------------- helpers ----------------
__device__ __forceinline__ uint32_t s2u(const void* p) {
    uint32_t a;
    asm("{ .reg .u64 t; cvta.to.shared.u64 t, %1; cvt.u32.u64 %0, t; }"
        : "=r"(a) : "l"(p));
    return a;
}
__device__ __forceinline__ void cp16(uint32_t d, const void* s) {
    asm volatile("cp.async.cg.shared.global [%0], [%1], 16;" :: "r"(d), "l"(s));
}
__device__ __forceinline__ void cp_commit() {
    asm volatile("cp.async.commit_group;" ::: "memory");
}
template <int N> __device__ __forceinline__ void cp_wait() {
    asm volatile("cp.async.wait_group %0;" :: "n"(N) : "memory");
}
__device__ __forceinline__ void ldsm4(uint32_t* r, uint32_t a) {
    asm volatile("ldmatrix.sync.aligned.m8n8.x4.shared.b16 {%0,%1,%2,%3}, [%4];"
        : "=r"(r[0]), "=r"(r[1]), "=r"(r[2]), "=r"(r[3]) : "r"(a));
}
__device__ __forceinline__ void mma16816(float* d, const uint32_t* a,
                                         uint32_t b0, uint32_t b1) {
    asm volatile("mma.sync.aligned.m16n8k16.row.col.f32.f16.f16.f32 "
        "{%0,%1,%2,%3}, {%4,%5,%6,%7}, {%8,%9}, {%0,%1,%2,%3};"
        : "+f"(d[0]), "+f"(d[1]), "+f"(d[2]), "+f"(d[3])
        : "r"(a[0]), "r"(a[1]), "r"(a[2]), "r"(a[3]), "r"(b0), "r"(b1));
}

// ---------------- convert kernel (single launch for x and w) ----------------
__global__ void __launch_bounds__(256)
k_convert(const float* __restrict__ x, const float* __restrict__ w,
          __half2* __restrict__ xh, __half2* __restrict__ xl,
          __half2* __restrict__ wh, size_t n4x, size_t n4tot) {
    size_t i = (size_t)blockIdx.x * blockDim.x + threadIdx.x;
    size_t stride = (size_t)gridDim.x * blockDim.x;
    for (; i < n4tot; i += stride) {
        if (i < n4x) {
            float4 v = ((const float4*)x)[i];
            __half h0 = __float2half_rn(v.x), h1 = __float2half_rn(v.y);
            __half h2 = __float2half_rn(v.z), h3 = __float2half_rn(v.w);
            __half l0 = __float2half_rn(v.x - __half2float(h0));
            __half l1 = __float2half_rn(v.y - __half2float(h1));
            __half l2 = __float2half_rn(v.z - __half2float(h2));
            __half l3 = __float2half_rn(v.w - __half2float(h3));
            xh[i * 2 + 0] = __halves2half2(h0, h1);
            xh[i * 2 + 1] = __halves2half2(h2, h3);
            xl[i * 2 + 0] = __halves2half2(l0, l1);
            xl[i * 2 + 1] = __halves2half2(l2, l3);
        } else {
            size_t idx = i - n4x;
            float4 v = ((const float4*)w)[idx];
            wh[idx * 2 + 0] = __halves2half2(__float2half_rn(v.x),
                                             __float2half_rn(v.y));
            wh[idx * 2 + 1] = __halves2half2(__float2half_rn(v.z),
                                             __float2half_rn(v.w));
        }
    }
}

// ---------------- fused GEMM (HMMA fp16 2-product, quarter-burst prefetch) ----------------
__global__ void __launch_bounds__(TPB, 2)
gemm_hmma(const float* __restrict__ bias, const float* __restrict__ gnw,
          const float* __restrict__ gnb, const float* __restrict__ mw,
          float* __restrict__ out) {
    extern __shared__ char smraw[];
    const uint32_t smb = s2u(smraw);

    const int tid = threadIdx.x;
    const int lane = tid & 31;
    const int wid = tid >> 5;
    const int warpM = wid >> 1;     // 0..3  (32 rows each)
    const int warpN = wid & 1;      // 0..1  (64 cols each)
    const int rowBase = blockIdx.y * BMt;
    const int colBase = blockIdx.x * BNt;

    // ---- loader mapping (proven R9) ----
    const bool isA = tid < 128;
    const int t6 = tid & 63;
    const int arowL = t6 >> 2;          // 0..15
    const int achunk = t6 & 3;
    const int wrowL = tid & 127;

    const char* gsrcA = (const char*)((tid < 64) ? g_xh : g_xl)
                      + (size_t)(rowBase + arowL) * (KDIM * 2) + achunk * 16;
    const uint32_t ldstA = smb + ((tid < 64) ? 0 : 8192) + arowL * 64
                         + (uint32_t)((achunk ^ ((arowL >> 1) & 3)) << 4);

    const char* gsrcW = (const char*)g_wh
                      + (size_t)(colBase + wrowL) * (KDIM * 2);
    const uint32_t wkey = (uint32_t)((wrowL >> 1) & 3);
    const uint32_t ldstW = smb + 16384 + wrowL * 64;

    // full chunk load (prologue only); NO commit
#define LOAD_ONE(kt_, s_) do {                                              \
        if (isA) {                                                          \
            const char* p_ = gsrcA + (size_t)(kt_) * 64;                    \
            uint32_t d_ = ldstA + (uint32_t)(s_) * STG_B;                   \
            _Pragma("unroll")                                               \
            for (int j_ = 0; j_ < 8; j_++)                                  \
                cp16(d_ + j_ * 1024, p_ + (size_t)j_ * 16 * (KDIM * 2));    \
        } else {                                                            \
            const char* p_ = gsrcW + (size_t)(kt_) * 64;                    \
            uint32_t d_ = ldstW + (uint32_t)(s_) * STG_B;                   \
            _Pragma("unroll")                                               \
            for (int j_ = 0; j_ < 4; j_++)                                  \
                cp16(d_ + ((((uint32_t)j_) ^ wkey) << 4), p_ + j_ * 16);    \
        }                                                                   \
    } while (0)

    // quarter-step load of the pair at hoisted bases (pfA/pfW, dfA/dfW);
    // st_ in 0..3.  A threads: 4 cp16 per step; W threads: 2 cp16 per step.
    // (chunk pair occupies slots base, base+1: (kt0+2)&3 is even)
#define LOAD_STEP4(st_) do {                                                \
        if (isA) {                                                          \
            _Pragma("unroll")                                               \
            for (int u_ = 0; u_ < 4; u_++) {                                \
                int idx_ = (st_) * 4 + u_;                                  \
                int c_ = idx_ >> 3, j_ = idx_ & 7;                          \
                cp16(dfA + c_ * STG_B + j_ * 1024,                          \
                     pfA + c_ * 64 + (size_t)j_ * 16 * (KDIM * 2));         \
            }                                                               \
        } else {                                                            \
            _Pragma("unroll")                                               \
            for (int u_ = 0; u_ < 2; u_++) {                                \
                int idx_ = (st_) * 2 + u_;                                  \
                int c_ = idx_ >> 2, j_ = idx_ & 3;                          \
                cp16(dfW + c_ * STG_B + ((((uint32_t)j_) ^ wkey) << 4),     \
                     pfW + c_ * 64 + j_ * 16);                              \
            }                                                               \
        }                                                                   \
    } while (0)

    // ---- ldsm lane address precompute ----
    uint32_t arow[2], akey[2];
#pragma unroll
    for (int mt = 0; mt < 2; mt++) {
        int r = warpM * 32 + mt * 16 + (lane & 7) + ((lane >> 3) & 1) * 8;
        arow[mt] = (uint32_t)(r * 64);
        akey[mt] = (uint32_t)((r >> 1) & 3);
    }
    const uint32_t asel = (uint32_t)((lane >> 4) & 1);
    uint32_t brow[4], bkey[4];
#pragma unroll
    for (int p = 0; p < 4; p++) {
        int r = warpN * 64 + p * 16 + (lane & 7) + ((lane >> 4) & 1) * 8;
        brow[p] = (uint32_t)(r * 64);
        bkey[p] = (uint32_t)((r >> 1) & 3);
    }
    const uint32_t bsel = (uint32_t)((lane >> 3) & 1);

    float acc[16][4];
#pragma unroll
    for (int i = 0; i < 16; i++)
#pragma unroll
        for (int j = 0; j < 4; j++) acc[i][j] = 0.f;

    LOAD_ONE(0, 0);
    LOAD_ONE(1, 1);
    cp_commit();                // kt 0,1 -> slots 0,1 (one group)

    for (int it = 0; it < NKT / 2; it++) {
        const int kt0 = 2 * it;
        cp_wait<0>();           // group for kt0,kt0+1 resident (committed mid-prev it)
        __syncthreads();        // reads of the other group finished

        // hoisted prefetch addressing for the (kt0+2, kt0+3) pair
        const bool pf = (kt0 + 2 < NKT);
        const char* pfA = gsrcA + (size_t)(kt0 + 2) * 64;
        const char* pfW = gsrcW + (size_t)(kt0 + 2) * 64;
        const uint32_t dfA = ldstA + (uint32_t)((kt0 + 2) & 3) * STG_B;
        const uint32_t dfW = ldstW + (uint32_t)((kt0 + 2) & 3) * STG_B;

#pragma unroll
        for (int q = 0; q < 2; q++) {
            const uint32_t Ab = smb + (uint32_t)((kt0 + q) & 3) * STG_B;
            const uint32_t Bb = Ab + 16384;
#pragma unroll
            for (int s = 0; s < 2; s++) {
                uint32_t ah[2][4], al[2][4], bh[8][2];
                // ALL fragment loads upfront: al latency hidden by ah-mma block
#pragma unroll
                for (int mt = 0; mt < 2; mt++) {
                    uint32_t ad = Ab + arow[mt]
                                + ((((uint32_t)s * 2 + asel) ^ akey[mt]) << 4);
                    ldsm4(ah[mt], ad);
                    ldsm4(al[mt], ad + 8192);
                }
#pragma unroll
                for (int p = 0; p < 4; p++) {
                    uint32_t bd = Bb + brow[p]
                                + ((((uint32_t)s * 2 + bsel) ^ bkey[p]) << 4);
                    uint32_t r1[4];
                    ldsm4(r1, bd);
                    bh[2 * p][0] = r1[0]; bh[2 * p][1] = r1[1];
                    bh[2 * p + 1][0] = r1[2]; bh[2 * p + 1][1] = r1[3];
                }
#pragma unroll
                for (int mt = 0; mt < 2; mt++)
#pragma unroll
                    for (int nt = 0; nt < 8; nt++)
                        mma16816(acc[mt * 8 + nt], ah[mt], bh[nt][0], bh[nt][1]);

                // quarter-burst prefetch: steps 0,2 after ah-mma of q0 s-blocks
                if (q == 0 && pf)
                    LOAD_STEP4(s * 2);

#pragma unroll
                for (int mt = 0; mt < 2; mt++)
#pragma unroll
                    for (int nt = 0; nt < 8; nt++)
                        mma16816(acc[mt * 8 + nt], al[mt], bh[nt][0], bh[nt][1]);

                // quarter-burst prefetch: steps 1,3 after al-mma of q0 s-blocks;
                // commit at the last q0 point -> full q1 of slack before the wait
                if (q == 0 && pf) {
                    LOAD_STEP4(s * 2 + 1);
                    if (s == 1) cp_commit();
                }
            }
        }
    }

    // ---------------- fused epilogue ----------------
    float biasv[16];
#pragma unroll
    for (int nt = 0; nt < 8; nt++) {
        int c0 = colBase + warpN * 64 + nt * 8 + 2 * (lane & 3);
        biasv[nt * 2]     = __ldg(bias + c0);
        biasv[nt * 2 + 1] = __ldg(bias + c0 + 1);
    }
#pragma unroll
    for (int mt = 0; mt < 2; mt++)
#pragma unroll
        for (int nt = 0; nt < 8; nt++) {
            acc[mt * 8 + nt][0] += biasv[nt * 2];
            acc[mt * 8 + nt][1] += biasv[nt * 2 + 1];
            acc[mt * 8 + nt][2] += biasv[nt * 2];
            acc[mt * 8 + nt][3] += biasv[nt * 2 + 1];
        }

    // per-thread partial row sums over this warp's 64 columns
    float rs[4], rq[4];
#pragma unroll
    for (int mt = 0; mt < 2; mt++) {
        float s0 = 0.f, q0 = 0.f, s1 = 0.f, q1 = 0.f;
#pragma unroll
        for (int nt = 0; nt < 8; nt++) {
            float v;
            v = acc[mt * 8 + nt][0]; s0 += v; q0 += v * v;
            v = acc[mt * 8 + nt][1]; s0 += v; q0 += v * v;
            v = acc[mt * 8 + nt][2]; s1 += v; q1 += v * v;
            v = acc[mt * 8 + nt][3]; s1 += v; q1 += v * v;
        }
        rs[mt * 2] = s0; rq[mt * 2] = q0;
        rs[mt * 2 + 1] = s1; rq[mt * 2 + 1] = q1;
    }
#pragma unroll
    for (int off = 1; off <= 2; off <<= 1)
#pragma unroll
        for (int i = 0; i < 4; i++) {
            rs[i] += __shfl_xor_sync(0xffffffffu, rs[i], off);
            rq[i] += __shfl_xor_sync(0xffffffffu, rq[i], off);
        }

    float2* red = (float2*)smraw;        // [128][2]
    __syncthreads();
    if ((lane & 3) == 0) {
#pragma unroll
        for (int mt = 0; mt < 2; mt++)
#pragma unroll
            for (int h = 0; h < 2; h++) {
                int rowL = warpM * 32 + mt * 16 + (lane >> 2) + h * 8;
                red[rowL * 2 + warpN] = make_float2(rs[mt * 2 + h], rq[mt * 2 + h]);
            }
    }
    __syncthreads();

    float meanv[4], rstdv[4];
#pragma unroll
    for (int mt = 0; mt < 2; mt++)
#pragma unroll
        for (int h = 0; h < 2; h++) {
            int rowL = warpM * 32 + mt * 16 + (lane >> 2) + h * 8;
            float2 t0 = red[rowL * 2 + 0];
            float2 t1 = red[rowL * 2 + 1];
            float s = t0.x + t1.x, q = t0.y + t1.y;
            float m = s * (1.0f / 128.0f);
            float var = q * (1.0f / 128.0f) - m * m;
            meanv[mt * 2 + h] = m;
            rstdv[mt * 2 + h] = rsqrtf(var + EPSV);
        }

    float gwv[16], gbv[16], mwv[16];
#pragma unroll
    for (int nt = 0; nt < 8; nt++) {
        int c0 = colBase + warpN * 64 + nt * 8 + 2 * (lane & 3);
        gwv[nt * 2] = __ldg(gnw + c0);   gwv[nt * 2 + 1] = __ldg(gnw + c0 + 1);
        gbv[nt * 2] = __ldg(gnb + c0);   gbv[nt * 2 + 1] = __ldg(gnb + c0 + 1);
        mwv[nt * 2] = __ldg(mw + c0);    mwv[nt * 2 + 1] = __ldg(mw + c0 + 1);
    }

#pragma unroll
    for (int mt = 0; mt < 2; mt++)
#pragma unroll
        for (int h = 0; h < 2; h++) {
            const int r = rowBase + warpM * 32 + mt * 16 + (lane >> 2) + h * 8;
            const float m = meanv[mt * 2 + h];
            const float rstd = rstdv[mt * 2 + h];
#pragma unroll
            for (int nt = 0; nt < 8; nt++) {
                const int c0 = colBase + warpN * 64 + nt * 8 + 2 * (lane & 3);
                float o2[2];
#pragma unroll
                for (int j = 0; j < 2; j++) {
                    float v = acc[mt * 8 + nt][h * 2 + j];
                    float hn = (v - m) * rstd;
                    hn = fmaf(hn, gwv[nt * 2 + j], gbv[nt * 2 + j]);
                    float x1 = __fdividef(hn, 1.0f + __expf(-hn));
                    float x2 = x1 * mwv[nt * 2 + j];
                    o2[j] = __fdividef(x2, 1.0f + __expf(-x2));
                }
                *(float2*)(out + (size_t)r * CDIM + c0) = make_float2(o2[0], o2[1]);
            }
        }
}

extern "C" void kernel_launch(void* const* d_in, const int* in_sizes, int n_in,
                              void* d_out, int out_size) {
    const float* x    = (const float*)d_in[0];
    const float* w    = (const float*)d_in[1];
    const float* bias = (const float*)d_in[2];
    const float* gnw  = (const float*)d_in[3];
    const float* gnb  = (const float*)d_in[4];
    const float* mw   = (const float*)d_in[5];
    float* out = (float*)d_out;

    const int rows = in_sizes[0] / KDIM;   // 8192

    __half *xh, *xl, *wh;
    cudaGetSymbolAddress((void**)&xh, g_xh);
    cudaGetSymbolAddress((void**)&xl, g_xl);
    cudaGetSymbolAddress((void**)&wh, g_wh);

    const size_t n4x = (size_t)rows * KDIM / 4;
    const size_t n4w = (size_t)CDIM * KDIM / 4;
    k_convert<<<4096, 256>>>(x, w, (__half2*)xh, (__half2*)xl,
                             (__half2*)wh, n4x, n4x + n4w);

    const int smem = NSTG * STG_B;     // 98304
    cudaFuncSetAttribute(gemm_hmma,
                         cudaFuncAttributeMaxDynamicSharedMemorySize, smem);

    dim3 grid(CDIM / BNt, rows / BMt);  // 32 x 64
    gemm_hmma<<<grid, TPB, smem>>>(bias, gnw, gnb, mw, out);
}

// round 17
// speedup vs baseline: 1.0881x; 1.0620x over previous
#include <cuda_runtime.h>
#include <cuda_fp16.h>
#include <cstdint>

#define KDIM 4096
#define CDIM 4096
#define BROWS 8192
#define EPSV 1e-5f

#define BMt 128
#define BNt 128
#define TPB 256
#define NSTG 4
#define STG_B 16384         // Ah(8K) Bh(8K)
#define NKT (KDIM / 32)     // 128

// fp16 scratch (device globals: sanctioned no-alloc workaround)
__device__ __half g_xh[(size_t)BROWS * KDIM];
__device__ __half g_wh[(size_t)CDIM * KDIM];

// ---------------- helpers ----------------
__device__ __forceinline__ uint32_t s2u(const void* p) {
    uint32_t a;
    asm("{ .reg .u64 t; cvta.to.shared.u64 t, %1; cvt.u32.u64 %0, t; }"
        : "=r"(a) : "l"(p));
    return a;
}
__device__ __forceinline__ void cp16(uint32_t d, const void* s) {
    asm volatile("cp.async.cg.shared.global [%0], [%1], 16;" :: "r"(d), "l"(s));
}
__device__ __forceinline__ void cp_commit() {
    asm volatile("cp.async.commit_group;" ::: "memory");
}
template <int N> __device__ __forceinline__ void cp_wait() {
    asm volatile("cp.async.wait_group %0;" :: "n"(N) : "memory");
}
__device__ __forceinline__ void ldsm4(uint32_t* r, uint32_t a) {
    asm volatile("ldmatrix.sync.aligned.m8n8.x4.shared.b16 {%0,%1,%2,%3}, [%4];"
        : "=r"(r[0]), "=r"(r[1]), "=r"(r[2]), "=r"(r[3]) : "r"(a));
}
__device__ __forceinline__ void mma16816(float* d, const uint32_t* a,
                                         uint32_t b0, uint32_t b1) {
    asm volatile("mma.sync.aligned.m16n8k16.row.col.f32.f16.f16.f32 "
        "{%0,%1,%2,%3}, {%4,%5,%6,%7}, {%8,%9}, {%0,%1,%2,%3};"
        : "+f"(d[0]), "+f"(d[1]), "+f"(d[2]), "+f"(d[3])
        : "r"(a[0]), "r"(a[1]), "r"(a[2]), "r"(a[3]), "r"(b0), "r"(b1));
}

// ---------------- convert kernel (single launch for x and w) ----------------
__global__ void __launch_bounds__(256)
k_convert(const float* __restrict__ x, const float* __restrict__ w,
          __half2* __restrict__ xh, __half2* __restrict__ wh,
          size_t n4x, size_t n4tot) {
    size_t i = (size_t)blockIdx.x * blockDim.x + threadIdx.x;
    size_t stride = (size_t)gridDim.x * blockDim.x;
    for (; i < n4tot; i += stride) {
        const float* s;
        __half2* d;
        size_t idx;
        if (i < n4x) { s = x; d = xh; idx = i; }
        else         { s = w; d = wh; idx = i - n4x; }
        float4 v = ((const float4*)s)[idx];
        d[idx * 2 + 0] = __halves2half2(__float2half_rn(v.x),
                                        __float2half_rn(v.y));
        d[idx * 2 + 1] = __halves2half2(__float2half_rn(v.z),
                                        __float2half_rn(v.w));
    }
}

// ---------------- fused GEMM (HMMA fp16 single-product) ----------------
__global__ void __launch_bounds__(TPB, 2)
gemm_hmma(const float* __restrict__ bias, const float* __restrict__ gnw,
          const float* __restrict__ gnb, const float* __restrict__ mw,
          float* __restrict__ out) {
    extern __shared__ char smraw[];
    const uint32_t smb = s2u(smraw);

    const int tid = threadIdx.x;
    const int lane = tid & 31;
    const int wid = tid >> 5;
    const int warpM = wid >> 1;     // 0..3  (32 rows each)
    const int warpN = wid & 1;      // 0..1  (64 cols each)
    const int rowBase = blockIdx.y * BMt;
    const int colBase = blockIdx.x * BNt;

    // ---- loader mapping: threads 0-127 -> xh rows, 128-255 -> wh rows ----
    const bool isA = tid < 128;
    const int lrow = tid & 127;         // row within tile
    const char* gsrc = isA
        ? (const char*)(g_xh + (size_t)(rowBase + lrow) * KDIM)
        : (const char*)(g_wh + (size_t)(colBase + lrow) * KDIM);
    const uint32_t lkey = (uint32_t)((lrow >> 1) & 3);
    const uint32_t ldst = smb + (isA ? 0 : 8192) + lrow * 64;

    // full chunk load (prologue only); NO commit. 4 cp16 per thread.
#define LOAD_ONE(kt_, s_) do {                                              \
        const char* p_ = gsrc + (size_t)(kt_) * 64;                         \
        uint32_t d_ = ldst + (uint32_t)(s_) * STG_B;                        \
        _Pragma("unroll")                                                   \
        for (int j_ = 0; j_ < 4; j_++)                                      \
            cp16(d_ + ((((uint32_t)j_) ^ lkey) << 4), p_ + j_ * 16);        \
    } while (0)

    // quarter-step load of the pair at hoisted bases (pfB, dfB);
    // st_ in 0..3, 2 cp16 per thread per step.
    // (chunk pair occupies slots base, base+1: (kt0+2)&3 is even)
#define LOAD_STEP4(st_) do {                                                \
        _Pragma("unroll")                                                   \
        for (int u_ = 0; u_ < 2; u_++) {                                    \
            int idx_ = (st_) * 2 + u_;                                      \
            int c_ = idx_ >> 2, j_ = idx_ & 3;                              \
            cp16(dfB + c_ * STG_B + ((((uint32_t)j_) ^ lkey) << 4),         \
                 pfB + c_ * 64 + j_ * 16);                                  \
        }                                                                   \
    } while (0)

    // ---- ldsm lane address precompute ----
    uint32_t arow[2], akey[2];
#pragma unroll
    for (int mt = 0; mt < 2; mt++) {
        int r = warpM * 32 + mt * 16 + (lane & 7) + ((lane >> 3) & 1) * 8;
        arow[mt] = (uint32_t)(r * 64);
        akey[mt] = (uint32_t)((r >> 1) & 3);
    }
    const uint32_t asel = (uint32_t)((lane >> 4) & 1);
    uint32_t brow[4], bkey[4];
#pragma unroll
    for (int p = 0; p < 4; p++) {
        int r = warpN * 64 + p * 16 + (lane & 7) + ((lane >> 4) & 1) * 8;
        brow[p] = (uint32_t)(r * 64);
        bkey[p] = (uint32_t)((r >> 1) & 3);
    }
    const uint32_t bsel = (uint32_t)((lane >> 3) & 1);

    float acc[16][4];
#pragma unroll
    for (int i = 0; i < 16; i++)
#pragma unroll
        for (int j = 0; j < 4; j++) acc[i][j] = 0.f;

    LOAD_ONE(0, 0);
    LOAD_ONE(1, 1);
    cp_commit();                // kt 0,1 -> slots 0,1 (one group)

    for (int it = 0; it < NKT / 2; it++) {
        const int kt0 = 2 * it;
        cp_wait<0>();           // group for kt0,kt0+1 resident (committed mid-prev it)
        __syncthreads();        // reads of the other group finished

        // hoisted prefetch addressing for the (kt0+2, kt0+3) pair
        const bool pf = (kt0 + 2 < NKT);
        const char* pfB = gsrc + (size_t)(kt0 + 2) * 64;
        const uint32_t dfB = ldst + (uint32_t)((kt0 + 2) & 3) * STG_B;

#pragma unroll
        for (int q = 0; q < 2; q++) {
            const uint32_t Ab = smb + (uint32_t)((kt0 + q) & 3) * STG_B;
            const uint32_t Bb = Ab + 8192;
#pragma unroll
            for (int s = 0; s < 2; s++) {
                uint32_t ah[2][4], bh[8][2];
#pragma unroll
                for (int mt = 0; mt < 2; mt++) {
                    uint32_t ad = Ab + arow[mt]
                                + ((((uint32_t)s * 2 + asel) ^ akey[mt]) << 4);
                    ldsm4(ah[mt], ad);
                }
#pragma unroll
                for (int p = 0; p < 4; p++) {
                    uint32_t bd = Bb + brow[p]
                                + ((((uint32_t)s * 2 + bsel) ^ bkey[p]) << 4);
                    uint32_t r1[4];
                    ldsm4(r1, bd);
                    bh[2 * p][0] = r1[0]; bh[2 * p][1] = r1[1];
                    bh[2 * p + 1][0] = r1[2]; bh[2 * p + 1][1] = r1[3];
                }

                // mma half 1 (mt=0)
#pragma unroll
                for (int nt = 0; nt < 8; nt++)
                    mma16816(acc[nt], ah[0], bh[nt][0], bh[nt][1]);
                if (q == 0 && pf) LOAD_STEP4(s * 2);

                // mma half 2 (mt=1)
#pragma unroll
                for (int nt = 0; nt < 8; nt++)
                    mma16816(acc[8 + nt], ah[1], bh[nt][0], bh[nt][1]);
                if (q == 0 && pf) {
                    LOAD_STEP4(s * 2 + 1);
                    if (s == 1) cp_commit();   // full q1 of slack before the wait
                }
            }
        }
    }

    // ---------------- fused epilogue ----------------
    float biasv[16];
#pragma unroll
    for (int nt = 0; nt < 8; nt++) {
        int c0 = colBase + warpN * 64 + nt * 8 + 2 * (lane & 3);
        biasv[nt * 2]     = __ldg(bias + c0);
        biasv[nt * 2 + 1] = __ldg(bias + c0 + 1);
    }
#pragma unroll
    for (int mt = 0; mt < 2; mt++)
#pragma unroll
        for (int nt = 0; nt < 8; nt++) {
            acc[mt * 8 + nt][0] += biasv[nt * 2];
            acc[mt * 8 + nt][1] += biasv[nt * 2 + 1];
            acc[mt * 8 + nt][2] += biasv[nt * 2];
            acc[mt * 8 + nt][3] += biasv[nt * 2 + 1];
        }

    // per-thread partial row sums over this warp's 64 columns
    float rs[4], rq[4];
#pragma unroll
    for (int mt = 0; mt < 2; mt++) {
        float s0 = 0.f, q0 = 0.f, s1 = 0.f, q1 = 0.f;
#pragma unroll
        for (int nt = 0; nt < 8; nt++) {
            float v;
            v = acc[mt * 8 + nt][0]; s0 += v; q0 += v * v;
            v = acc[mt * 8 + nt][1]; s0 += v; q0 += v * v;
            v = acc[mt * 8 + nt][2]; s1 += v; q1 += v * v;
            v = acc[mt * 8 + nt][3]; s1 += v; q1 += v * v;
        }
        rs[mt * 2] = s0; rq[mt * 2] = q0;
        rs[mt * 2 + 1] = s1; rq[mt * 2 + 1] = q1;
    }
#pragma unroll
    for (int off = 1; off <= 2; off <<= 1)
#pragma unroll
        for (int i = 0; i < 4; i++) {
            rs[i] += __shfl_xor_sync(0xffffffffu, rs[i], off);
            rq[i] += __shfl_xor_sync(0xffffffffu, rq[i], off);
        }

    float2* red = (float2*)smraw;        // [128][2]
    __syncthreads();
    if ((lane & 3) == 0) {
#pragma unroll
        for (int mt = 0; mt < 2; mt++)
#pragma unroll
            for (int h = 0; h < 2; h++) {
                int rowL = warpM * 32 + mt * 16 + (lane >> 2) + h * 8;
                red[rowL * 2 + warpN] = make_float2(rs[mt * 2 + h], rq[mt * 2 + h]);
            }
    }
    __syncthreads();

    float meanv[4], rstdv[4];
#pragma unroll
    for (int mt = 0; mt < 2; mt++)
#pragma unroll
        for (int h = 0; h < 2; h++) {
            int rowL = warpM * 32 + mt * 16 + (lane >> 2) + h * 8;
            float2 t0 = red[rowL * 2 + 0];
            float2 t1 = red[rowL * 2 + 1];
            float s = t0.x + t1.x, q = t0.y + t1.y;
            float m = s * (1.0f / 128.0f);
            float var = q * (1.0f / 128.0f) - m * m;
            meanv[mt * 2 + h] = m;
            rstdv[mt * 2 + h] = rsqrtf(var + EPSV);
        }

    float gwv[16], gbv[16], mwv[16];
#pragma unroll
    for (int nt = 0; nt < 8; nt++) {
        int c0 = colBase + warpN * 64 + nt * 8 + 2 * (lane & 3);
        gwv[nt * 2] = __ldg(gnw + c0);   gwv[nt * 2 + 1] = __ldg(gnw + c0 + 1);
        gbv[nt * 2] = __ldg(gnb + c0);   gbv[nt * 2 + 1] = __ldg(gnb + c0 + 1);
        mwv[nt * 2] = __ldg(mw + c0);    mwv[nt * 2 + 1] = __ldg(mw + c0 + 1);
    }

#pragma unroll
    for (int mt = 0; mt < 2; mt++)
#pragma unroll
        for (int h = 0; h < 2; h++) {
            const int r = rowBase + warpM * 32 + mt * 16 + (lane >> 2) + h * 8;
            const float m = meanv[mt * 2 + h];
            const float rstd = rstdv[mt * 2 + h];
#pragma unroll
            for (int nt = 0; nt < 8; nt++) {
                const int c0 = colBase + warpN * 64 + nt * 8 + 2 * (lane & 3);
                float o2[2];
#pragma unroll
                for (int j = 0; j < 2; j++) {
                    float v = acc[mt * 8 + nt][h * 2 + j];
                    float hn = (v - m) * rstd;
                    hn = fmaf(hn, gwv[nt * 2 + j], gbv[nt * 2 + j]);
                    float x1 = __fdividef(hn, 1.0f + __expf(-hn));
                    float x2 = x1 * mwv[nt * 2 + j];
                    o2[j] = __fdividef(x2, 1.0f + __expf(-x2));
                }
                *(float2*)(out + (size_t)r * CDIM + c0) = make_float2(o2[0], o2[1]);
            }
        }
}

extern "C" void kernel_launch(void* const* d_in, const int* in_sizes, int n_in,
                              void* d_out, int out_size) {
    const float* x    = (const float*)d_in[0];
    const float* w    = (const float*)d_in[1];
    const float* bias = (const float*)d_in[2];
    const float* gnw  = (const float*)d_in[3];
    const float* gnb  = (const float*)d_in[4];
    const float* mw   = (const float*)d_in[5];
    float* out = (float*)d_out;

    const int rows = in_sizes[0] / KDIM;   // 8192

    __half *xh, *wh;
    cudaGetSymbolAddress((void**)&xh, g_xh);
    cudaGetSymbolAddress((void**)&wh, g_wh);

    const size_t n4x = (size_t)rows * KDIM / 4;
    const size_t n4w = (size_t)CDIM * KDIM / 4;
    k_convert<<<4096, 256>>>(x, w, (__half2*)xh, (__half2*)wh,
                             n4x, n4x + n4w);

    const int smem = NSTG * STG_B;     // 65536
    cudaFuncSetAttribute(gemm_hmma,
                         cudaFuncAttributeMaxDynamicSharedMemorySize, smem);

    dim3 grid(CDIM / BNt, rows / BMt);  // 32 x 64
    gemm_hmma<<<grid, TPB, smem>>>(bias, gnw, gnb, mw, out);
}